// round 4
// baseline (speedup 1.0000x reference)
#include <cuda_runtime.h>
#include <math.h>
#include <stddef.h>

#define Bq   4096
#define Tt   512
#define IND  17
#define LATD 256
#define HID  512
#define G3   1536
#define KIH  257          // LATD + 1 (dt)
#define MB   16           // batch rows per block
#define NBLK (Bq / MB)    // 256 blocks
#define NTHR 512
#define SPAD 20           // smem row pad (floats): 80B rows -> float4-aligned

// ---- device scratch (static, no runtime allocation) ----
__device__ float g_w1T[IND * LATD];    // [k][j]
__device__ float g_w2T[LATD * LATD];   // [k][j]
__device__ float g_wihT[KIH * G3];     // [k][j]
__device__ float g_whhT[HID * G3];     // [k][j]
__device__ float g_hbuf[2][(size_t)Bq * HID];

// ---- one-time weight transpose (runs each replay; ~5MB, negligible) ----
__global__ void transpose_weights_kernel(const float* __restrict__ w1,
                                         const float* __restrict__ w2,
                                         const float* __restrict__ wih,
                                         const float* __restrict__ whh) {
    int i = blockIdx.x * blockDim.x + threadIdx.x;
    int stride = gridDim.x * blockDim.x;
    for (int o = i; o < IND * LATD; o += stride) {
        int k = o / LATD, j = o % LATD;
        g_w1T[o] = w1[j * IND + k];
    }
    for (int o = i; o < LATD * LATD; o += stride) {
        int k = o / LATD, j = o % LATD;
        g_w2T[o] = w2[j * LATD + k];
    }
    for (int o = i; o < KIH * G3; o += stride) {
        int k = o / G3, j = o % G3;
        g_wihT[o] = wih[j * KIH + k];
    }
    for (int o = i; o < HID * G3; o += stride) {
        int k = o / G3, j = o % G3;
        g_whhT[o] = whh[j * HID + k];
    }
}

__device__ __forceinline__ float sigmoidf_acc(float v) {
    return 1.0f / (1.0f + expf(-v));
}

// ---- fused per-timestep kernel: encoder + GRU cell + heads + dp accumulate ----
__global__ void __launch_bounds__(NTHR, 1)
gru_step_kernel(const float* __restrict__ x,
                const float* __restrict__ h0,
                float* __restrict__ dp_out,
                const float* __restrict__ b1, const float* __restrict__ b2,
                const float* __restrict__ bih, const float* __restrict__ bhh,
                const float* __restrict__ qw, const float* __restrict__ qb,
                const float* __restrict__ vw, const float* __restrict__ vb,
                const float* __restrict__ cw, const float* __restrict__ cb,
                int t) {
    extern __shared__ float sm[];
    float* s_h   = sm;                       // [HID][SPAD]  h (old, then new), k-major
    float* s_gin = s_h + HID * SPAD;         // [KIH][SPAD]  encoder output + dt, k-major
    float* s_z1  = s_gin + KIH * SPAD;       // [LATD][SPAD] encoder layer-1, k-major
    float* s_x   = s_z1 + LATD * SPAD;       // [MB][IND]    raw x tile, row-major

    const int tid = threadIdx.x;
    const int b0  = blockIdx.x * MB;

    const float* hin  = (t == 0) ? h0 : ((t & 1) ? g_hbuf[0] : g_hbuf[1]);
    float*       hout = (t & 1) ? g_hbuf[1] : g_hbuf[0];

    // ---- stage 0: load x tile and h tile (transposed) ----
    for (int idx = tid; idx < MB * IND; idx += NTHR) {
        int m = idx / IND, c = idx % IND;
        s_x[idx] = x[((size_t)(b0 + m) * Tt + t) * IND + c];
    }
    for (int idx = tid; idx < MB * HID; idx += NTHR) {
        int m = idx >> 9;           // idx / 512
        int k = idx & (HID - 1);    // coalesced over k
        s_h[k * SPAD + m] = hin[(size_t)(b0 + m) * HID + k];
    }
    __syncthreads();

    const int j    = tid & (LATD - 1);
    const int half = tid >> 8;      // 0 or 1
    const int mb   = half * 8;      // this thread handles rows mb..mb+7 in encoder

    // ---- stage 1: z1 = relu(x @ w1^T + b1) ----
    {
        float acc[8];
#pragma unroll
        for (int i = 0; i < 8; i++) acc[i] = 0.0f;
#pragma unroll
        for (int k = 0; k < IND; k++) {
            float w = g_w1T[k * LATD + j];
#pragma unroll
            for (int i = 0; i < 8; i++) acc[i] += s_x[(mb + i) * IND + k] * w;
        }
        float bb = b1[j];
#pragma unroll
        for (int i = 0; i < 8; i++) s_z1[j * SPAD + mb + i] = fmaxf(acc[i] + bb, 0.0f);
    }
    __syncthreads();

    // ---- stage 2: lat = relu(z1 @ w2^T + b2); gin = [lat, dt] ----
    {
        float acc[8];
#pragma unroll
        for (int i = 0; i < 8; i++) acc[i] = 0.0f;
        const float* wp = g_w2T + j;
        const float* zp = s_z1 + mb;
        for (int k = 0; k < LATD; k++) {
            float w = wp[0];
            const float4* z4 = reinterpret_cast<const float4*>(zp);
            float4 a = z4[0], b = z4[1];
            acc[0] += a.x * w; acc[1] += a.y * w; acc[2] += a.z * w; acc[3] += a.w * w;
            acc[4] += b.x * w; acc[5] += b.y * w; acc[6] += b.z * w; acc[7] += b.w * w;
            wp += LATD;
            zp += SPAD;
        }
        float bb = b2[j];
#pragma unroll
        for (int i = 0; i < 8; i++) s_gin[j * SPAD + mb + i] = fmaxf(acc[i] + bb, 0.0f);
    }
    if (tid < MB) {
        s_gin[LATD * SPAD + tid] = s_x[tid * IND + (IND - 1)];  // dt row (k = 256)
    }
    __syncthreads();

    // ---- stage 3: fused gate GEMMs. thread jj owns hidden unit jj for 16 rows ----
    const int jj = tid;  // 0..511
    float ar[MB], az[MB], an[MB], hn[MB];
    {
        float br  = bih[jj]           + bhh[jj];
        float bz  = bih[jj + HID]     + bhh[jj + HID];
        float bni = bih[jj + 2 * HID];
#pragma unroll
        for (int m = 0; m < MB; m++) { ar[m] = br; az[m] = bz; an[m] = bni; hn[m] = 0.0f; }
    }

    // input-side: k over gin (257), accumulate ar/az/an
    {
        const float* wp = g_wihT + jj;
        const float* gp = s_gin;
        for (int k = 0; k < KIH; k++) {
            float wr = wp[0];
            float wz = wp[HID];
            float wn = wp[2 * HID];
            const float4* g4 = reinterpret_cast<const float4*>(gp);
            float4 p0 = g4[0], p1 = g4[1], p2 = g4[2], p3 = g4[3];
            float v[16] = {p0.x, p0.y, p0.z, p0.w, p1.x, p1.y, p1.z, p1.w,
                           p2.x, p2.y, p2.z, p2.w, p3.x, p3.y, p3.z, p3.w};
#pragma unroll
            for (int m = 0; m < 16; m++) {
                ar[m] += v[m] * wr;
                az[m] += v[m] * wz;
                an[m] += v[m] * wn;
            }
            wp += G3;
            gp += SPAD;
        }
    }
    // recurrent-side: k over h (512), accumulate ar/az/hn
    {
        const float* wp = g_whhT + jj;
        const float* hp = s_h;
        for (int k = 0; k < HID; k++) {
            float wr = wp[0];
            float wz = wp[HID];
            float wn = wp[2 * HID];
            const float4* h4 = reinterpret_cast<const float4*>(hp);
            float4 p0 = h4[0], p1 = h4[1], p2 = h4[2], p3 = h4[3];
            float v[16] = {p0.x, p0.y, p0.z, p0.w, p1.x, p1.y, p1.z, p1.w,
                           p2.x, p2.y, p2.z, p2.w, p3.x, p3.y, p3.z, p3.w};
#pragma unroll
            for (int m = 0; m < 16; m++) {
                ar[m] += v[m] * wr;
                az[m] += v[m] * wz;
                hn[m] += v[m] * wn;
            }
            wp += G3;
            hp += SPAD;
        }
    }

    // GRU update
    float hnew[MB];
    {
        float bnh = bhh[jj + 2 * HID];
#pragma unroll
        for (int m = 0; m < MB; m++) {
            float r    = sigmoidf_acc(ar[m]);
            float z    = sigmoidf_acc(az[m]);
            float n    = tanhf(an[m] + r * (hn[m] + bnh));
            float hold = s_h[jj * SPAD + m];
            hnew[m]    = (1.0f - z) * n + z * hold;
        }
    }
    __syncthreads();  // everyone done reading old s_h
#pragma unroll
    for (int m = 0; m < MB; m++) {
        s_h[jj * SPAD + m] = hnew[m];
        hout[(size_t)(b0 + m) * HID + jj] = hnew[m];
    }
    __syncthreads();

    // ---- stage 4: heads. one warp per sample ----
    {
        const int lane = tid & 31;
        const int m    = tid >> 5;  // 0..15
        float aq0 = 0.f, aq1 = 0.f, aq2 = 0.f, aq3 = 0.f;
        float av0 = 0.f, av1 = 0.f, av2 = 0.f;
        float ac0 = 0.f, ac1 = 0.f, ac2 = 0.f;
#pragma unroll
        for (int it = 0; it < HID / 32; it++) {
            int k = lane + it * 32;
            float hv = s_h[k * SPAD + m];
            aq0 += hv * qw[k];
            aq1 += hv * qw[HID + k];
            aq2 += hv * qw[2 * HID + k];
            aq3 += hv * qw[3 * HID + k];
            av0 += hv * vw[k];
            av1 += hv * vw[HID + k];
            av2 += hv * vw[2 * HID + k];
            ac0 += hv * cw[k];
            ac1 += hv * cw[HID + k];
            ac2 += hv * cw[2 * HID + k];
        }
#pragma unroll
        for (int off = 16; off > 0; off >>= 1) {
            aq0 += __shfl_xor_sync(0xffffffffu, aq0, off);
            aq1 += __shfl_xor_sync(0xffffffffu, aq1, off);
            aq2 += __shfl_xor_sync(0xffffffffu, aq2, off);
            aq3 += __shfl_xor_sync(0xffffffffu, aq3, off);
            av0 += __shfl_xor_sync(0xffffffffu, av0, off);
            av1 += __shfl_xor_sync(0xffffffffu, av1, off);
            av2 += __shfl_xor_sync(0xffffffffu, av2, off);
            ac0 += __shfl_xor_sync(0xffffffffu, ac0, off);
            ac1 += __shfl_xor_sync(0xffffffffu, ac1, off);
            ac2 += __shfl_xor_sync(0xffffffffu, ac2, off);
        }
        if (lane == 0) {
            float q0 = aq0 + qb[0], q1 = aq1 + qb[1], q2 = aq2 + qb[2], q3 = aq3 + qb[3];
            float nrm = sqrtf(q0 * q0 + q1 * q1 + q2 * q2 + q3 * q3);
            nrm = fmaxf(nrm, 1e-12f);
            float w = q0 / nrm, xq = q1 / nrm, yq = q2 / nrm, zq = q3 / nrm;
            float xx = xq * xq, yy = yq * yq, zz = zq * zq;
            float xy = xq * yq, xz = xq * zq, yz = yq * zq;
            float wx = w * xq, wy = w * yq, wz2 = w * zq;
            float a0 = s_x[m * IND + 0], a1 = s_x[m * IND + 1], a2 = s_x[m * IND + 2];
            float dt = s_x[m * IND + (IND - 1)];
            float aw0 = (1.f - 2.f * (yy + zz)) * a0 + 2.f * (xy - wz2) * a1 + 2.f * (xz + wy) * a2;
            float aw1 = 2.f * (xy + wz2) * a0 + (1.f - 2.f * (xx + zz)) * a1 + 2.f * (yz - wx) * a2;
            float aw2 = 2.f * (xz - wy) * a0 + 2.f * (yz + wx) * a1 + (1.f - 2.f * (xx + yy)) * a2;
            float v0 = av0 + vb[0], v1 = av1 + vb[1], v2 = av2 + vb[2];
            float e0 = ac0 + cb[0], e1 = ac1 + cb[1], e2 = ac2 + cb[2];
            float hdt2 = 0.5f * dt * dt;
            size_t ob = (size_t)(b0 + m) * 3;
            dp_out[ob + 0] += v0 * dt + aw0 * hdt2 + e0;
            dp_out[ob + 1] += v1 * dt + aw1 * hdt2 + e1;
            dp_out[ob + 2] += v2 * dt + aw2 * hdt2 + e2;
        }
    }
}

extern "C" void kernel_launch(void* const* d_in, const int* in_sizes, int n_in,
                              void* d_out, int out_size) {
    (void)in_sizes; (void)n_in;
    const float* x   = (const float*)d_in[0];
    const float* h0  = (const float*)d_in[1];
    const float* w1  = (const float*)d_in[2];
    const float* b1  = (const float*)d_in[3];
    const float* w2  = (const float*)d_in[4];
    const float* b2  = (const float*)d_in[5];
    const float* wih = (const float*)d_in[6];
    const float* whh = (const float*)d_in[7];
    const float* bih = (const float*)d_in[8];
    const float* bhh = (const float*)d_in[9];
    const float* qw  = (const float*)d_in[10];
    const float* qb  = (const float*)d_in[11];
    const float* vw  = (const float*)d_in[12];
    const float* vb  = (const float*)d_in[13];
    const float* cw  = (const float*)d_in[14];
    const float* cb  = (const float*)d_in[15];
    float* out = (float*)d_out;

    const size_t smem_bytes =
        (size_t)(HID * SPAD + KIH * SPAD + LATD * SPAD + MB * IND) * sizeof(float);

    cudaFuncSetAttribute(gru_step_kernel,
                         cudaFuncAttributeMaxDynamicSharedMemorySize,
                         (int)smem_bytes);

    cudaMemsetAsync(d_out, 0, (size_t)out_size * sizeof(float));
    transpose_weights_kernel<<<128, 256>>>(w1, w2, wih, whh);

    for (int t = 0; t < Tt; t++) {
        gru_step_kernel<<<NBLK, NTHR, smem_bytes>>>(
            x, h0, out, b1, b2, bih, bhh, qw, qb, vw, vb, cw, cb, t);
    }
}

// round 5
// speedup vs baseline: 1.2707x; 1.2707x over previous
#include <cuda_runtime.h>
#include <math.h>
#include <stddef.h>

typedef unsigned long long ull;

#define Bq   4096
#define Tt   512
#define IND  17
#define LATD 256
#define HID  512
#define G3   1536
#define KIH  257          // LATD + 1 (dt)
#define MB   16           // batch rows per block
#define NBLK (Bq / MB)    // 256 blocks
#define NTHR 512
#define SPAD 20           // smem row pad (floats): 80B rows -> 16B-aligned

// ---- device scratch (static, no runtime allocation) ----
// +1 padded row on each transposed weight array: the software-pipelined
// prefetch reads one row past the end on the final iteration (values unused).
__device__ float g_w1T[IND * LATD];            // [k][j]
__device__ float g_w2T[(LATD + 1) * LATD];     // [k][j] (+pad row)
__device__ float g_wihT[(KIH + 1) * G3];       // [k][j] (+pad row)
__device__ float g_whhT[(HID + 1) * G3];       // [k][j] (+pad row)

// ---- packed f32x2 helpers (Blackwell FFMA2 — ptxas never emits these) ----
__device__ __forceinline__ ull pack2(float v) {
    ull r;
    asm("mov.b64 %0, {%1, %1};" : "=l"(r) : "f"(v));
    return r;
}
__device__ __forceinline__ void fma2(ull& d, ull a, ull b) {
    asm("fma.rn.f32x2 %0, %1, %2, %0;" : "+l"(d) : "l"(a), "l"(b));
}
__device__ __forceinline__ float2 unpack2(ull v) {
    float2 f;
    asm("mov.b64 {%0, %1}, %2;" : "=f"(f.x), "=f"(f.y) : "l"(v));
    return f;
}

// ---- one-time weight transpose ----
__global__ void transpose_weights_kernel(const float* __restrict__ w1,
                                         const float* __restrict__ w2,
                                         const float* __restrict__ wih,
                                         const float* __restrict__ whh) {
    int i = blockIdx.x * blockDim.x + threadIdx.x;
    int stride = gridDim.x * blockDim.x;
    for (int o = i; o < IND * LATD; o += stride) {
        int k = o / LATD, j = o % LATD;
        g_w1T[o] = w1[j * IND + k];
    }
    for (int o = i; o < LATD * LATD; o += stride) {
        int k = o / LATD, j = o % LATD;
        g_w2T[o] = w2[j * LATD + k];
    }
    for (int o = i; o < KIH * G3; o += stride) {
        int k = o / G3, j = o % G3;
        g_wihT[o] = wih[j * KIH + k];
    }
    for (int o = i; o < HID * G3; o += stride) {
        int k = o / G3, j = o % G3;
        g_whhT[o] = whh[j * HID + k];
    }
}

__device__ __forceinline__ float sigmoidf_acc(float v) {
    return 1.0f / (1.0f + expf(-v));
}

// ---- persistent fused kernel: each block owns a 16-sample batch tile for all
// 512 timesteps. h lives in SMEM across the whole sequence; dp accumulates in
// registers; one global write at the end. Blocks are fully independent. ----
__global__ void __launch_bounds__(NTHR, 1)
imu_persistent_kernel(const float* __restrict__ x,
                      const float* __restrict__ h0,
                      float* __restrict__ dp_out,
                      const float* __restrict__ b1, const float* __restrict__ b2,
                      const float* __restrict__ bih, const float* __restrict__ bhh,
                      const float* __restrict__ qw, const float* __restrict__ qb,
                      const float* __restrict__ vw, const float* __restrict__ vb,
                      const float* __restrict__ cw, const float* __restrict__ cb) {
    extern __shared__ float sm[];
    float* s_h   = sm;                       // [HID][SPAD]  h, k-major
    float* s_gin = s_h + HID * SPAD;         // [KIH][SPAD]  encoder output + dt
    float* s_z1  = s_gin + KIH * SPAD;       // [LATD][SPAD] encoder layer-1
    float* s_x   = s_z1 + LATD * SPAD;       // [MB][IND]    raw x tile

    const int tid  = threadIdx.x;
    const int b0   = blockIdx.x * MB;
    const int j    = tid & (LATD - 1);
    const int mb   = (tid >> 8) * 8;         // encoder row group: 0 or 8
    const int jj   = tid;                    // hidden unit owned in gate GEMM
    const int lane = tid & 31;
    const int m    = tid >> 5;               // sample owned in heads stage

    // hoisted per-thread constants
    const float bj1 = b1[j];
    const float bj2 = b2[j];
    const float br  = bih[jj]           + bhh[jj];
    const float bz  = bih[jj + HID]     + bhh[jj + HID];
    const float bni = bih[jj + 2 * HID];
    const float bnh = bhh[jj + 2 * HID];

    float dp0 = 0.f, dp1 = 0.f, dp2 = 0.f;   // lane 0 of each warp holds sample m's dp

    // load h0 once (transposed into SMEM)
    for (int idx = tid; idx < MB * HID; idx += NTHR) {
        int mm = idx >> 9;
        int k  = idx & (HID - 1);
        s_h[k * SPAD + mm] = h0[(size_t)(b0 + mm) * HID + k];
    }

    for (int t = 0; t < Tt; t++) {
        __syncthreads();  // protect s_x / s_z1 / s_gin vs previous step's readers

        // ---- stage 0: load x tile ----
        for (int idx = tid; idx < MB * IND; idx += NTHR) {
            int mm = idx / IND, c = idx % IND;
            s_x[idx] = x[((size_t)(b0 + mm) * Tt + t) * IND + c];
        }
        __syncthreads();

        // ---- stage 1: z1 = relu(x @ w1^T + b1) ----
        {
            float acc[8];
#pragma unroll
            for (int i = 0; i < 8; i++) acc[i] = 0.0f;
#pragma unroll
            for (int k = 0; k < IND; k++) {
                float w = g_w1T[k * LATD + j];
#pragma unroll
                for (int i = 0; i < 8; i++) acc[i] += s_x[(mb + i) * IND + k] * w;
            }
#pragma unroll
            for (int i = 0; i < 8; i++)
                s_z1[j * SPAD + mb + i] = fmaxf(acc[i] + bj1, 0.0f);
        }
        __syncthreads();

        // ---- stage 2: lat = relu(z1 @ w2^T + b2) -> s_gin (packed f32x2) ----
        {
            ull acc[4];
#pragma unroll
            for (int i = 0; i < 4; i++) acc[i] = 0ULL;
            const float* wp = g_w2T + j;
            float w = wp[0];
            for (int k = 0; k < LATD; k++) {
                float wnext = wp[LATD];  // prefetch (pad row on last iter)
                ull w2 = pack2(w);
                const ulonglong2* z2 =
                    reinterpret_cast<const ulonglong2*>(s_z1 + k * SPAD + mb);
                ulonglong2 a = z2[0], b = z2[1];
                fma2(acc[0], a.x, w2);
                fma2(acc[1], a.y, w2);
                fma2(acc[2], b.x, w2);
                fma2(acc[3], b.y, w2);
                w = wnext;
                wp += LATD;
            }
#pragma unroll
            for (int i = 0; i < 4; i++) {
                float2 f = unpack2(acc[i]);
                s_gin[j * SPAD + mb + 2 * i]     = fmaxf(f.x + bj2, 0.0f);
                s_gin[j * SPAD + mb + 2 * i + 1] = fmaxf(f.y + bj2, 0.0f);
            }
        }
        if (tid < MB) {
            s_gin[LATD * SPAD + tid] = s_x[tid * IND + (IND - 1)];  // dt row (k=256)
        }
        __syncthreads();

        // ---- stage 3: fused gate GEMMs (packed f32x2), thread jj owns 16 rows ----
        ull ar2[8], az2[8], an2[8], hn2[8];
        {
            ull brp = pack2(br), bzp = pack2(bz), bnp = pack2(bni);
#pragma unroll
            for (int i = 0; i < 8; i++) {
                ar2[i] = brp; az2[i] = bzp; an2[i] = bnp; hn2[i] = 0ULL;
            }
        }
        // input side: k over gin (257) -> ar/az/an
        {
            const float* wp = g_wihT + jj;
            const float* gp = s_gin;
            float wr = wp[0], wz = wp[HID], wn = wp[2 * HID];
            for (int k = 0; k < KIH; k++) {
                const float* wq = wp + G3;
                float nwr = wq[0], nwz = wq[HID], nwn = wq[2 * HID];  // prefetch
                ull wr2 = pack2(wr), wz2 = pack2(wz), wn2 = pack2(wn);
                const ulonglong2* g2 = reinterpret_cast<const ulonglong2*>(gp);
                ulonglong2 p0 = g2[0], p1 = g2[1], p2 = g2[2], p3 = g2[3];
                fma2(ar2[0], p0.x, wr2); fma2(az2[0], p0.x, wz2); fma2(an2[0], p0.x, wn2);
                fma2(ar2[1], p0.y, wr2); fma2(az2[1], p0.y, wz2); fma2(an2[1], p0.y, wn2);
                fma2(ar2[2], p1.x, wr2); fma2(az2[2], p1.x, wz2); fma2(an2[2], p1.x, wn2);
                fma2(ar2[3], p1.y, wr2); fma2(az2[3], p1.y, wz2); fma2(an2[3], p1.y, wn2);
                fma2(ar2[4], p2.x, wr2); fma2(az2[4], p2.x, wz2); fma2(an2[4], p2.x, wn2);
                fma2(ar2[5], p2.y, wr2); fma2(az2[5], p2.y, wz2); fma2(an2[5], p2.y, wn2);
                fma2(ar2[6], p3.x, wr2); fma2(az2[6], p3.x, wz2); fma2(an2[6], p3.x, wn2);
                fma2(ar2[7], p3.y, wr2); fma2(az2[7], p3.y, wz2); fma2(an2[7], p3.y, wn2);
                wr = nwr; wz = nwz; wn = nwn;
                wp = wq;
                gp += SPAD;
            }
        }
        // recurrent side: k over h (512) -> ar/az/hn
        {
            const float* wp = g_whhT + jj;
            const float* hp = s_h;
            float wr = wp[0], wz = wp[HID], wn = wp[2 * HID];
            for (int k = 0; k < HID; k++) {
                const float* wq = wp + G3;
                float nwr = wq[0], nwz = wq[HID], nwn = wq[2 * HID];  // prefetch
                ull wr2 = pack2(wr), wz2 = pack2(wz), wn2 = pack2(wn);
                const ulonglong2* h2 = reinterpret_cast<const ulonglong2*>(hp);
                ulonglong2 p0 = h2[0], p1 = h2[1], p2 = h2[2], p3 = h2[3];
                fma2(ar2[0], p0.x, wr2); fma2(az2[0], p0.x, wz2); fma2(hn2[0], p0.x, wn2);
                fma2(ar2[1], p0.y, wr2); fma2(az2[1], p0.y, wz2); fma2(hn2[1], p0.y, wn2);
                fma2(ar2[2], p1.x, wr2); fma2(az2[2], p1.x, wz2); fma2(hn2[2], p1.x, wn2);
                fma2(ar2[3], p1.y, wr2); fma2(az2[3], p1.y, wz2); fma2(hn2[3], p1.y, wn2);
                fma2(ar2[4], p2.x, wr2); fma2(az2[4], p2.x, wz2); fma2(hn2[4], p2.x, wn2);
                fma2(ar2[5], p2.y, wr2); fma2(az2[5], p2.y, wz2); fma2(hn2[5], p2.y, wn2);
                fma2(ar2[6], p3.x, wr2); fma2(az2[6], p3.x, wz2); fma2(hn2[6], p3.x, wn2);
                fma2(ar2[7], p3.y, wr2); fma2(az2[7], p3.y, wz2); fma2(hn2[7], p3.y, wn2);
                wr = nwr; wz = nwz; wn = nwn;
                wp = wq;
                hp += SPAD;
            }
        }

        // ---- GRU update ----
        float hnew[MB];
#pragma unroll
        for (int i = 0; i < 8; i++) {
            float2 fr = unpack2(ar2[i]);
            float2 fz = unpack2(az2[i]);
            float2 fn = unpack2(an2[i]);
            float2 fh = unpack2(hn2[i]);
            {
                float r    = sigmoidf_acc(fr.x);
                float z    = sigmoidf_acc(fz.x);
                float n    = tanhf(fn.x + r * (fh.x + bnh));
                float hold = s_h[jj * SPAD + 2 * i];
                hnew[2 * i] = (1.0f - z) * n + z * hold;
            }
            {
                float r    = sigmoidf_acc(fr.y);
                float z    = sigmoidf_acc(fz.y);
                float n    = tanhf(fn.y + r * (fh.y + bnh));
                float hold = s_h[jj * SPAD + 2 * i + 1];
                hnew[2 * i + 1] = (1.0f - z) * n + z * hold;
            }
        }
        __syncthreads();  // everyone done reading old s_h
#pragma unroll
        for (int mm = 0; mm < MB; mm++) s_h[jj * SPAD + mm] = hnew[mm];
        __syncthreads();

        // ---- stage 4: heads. one warp per sample; lane0 accumulates dp ----
        {
            float aq0 = 0.f, aq1 = 0.f, aq2 = 0.f, aq3 = 0.f;
            float av0 = 0.f, av1 = 0.f, av2 = 0.f;
            float ac0 = 0.f, ac1 = 0.f, ac2 = 0.f;
#pragma unroll
            for (int it = 0; it < HID / 32; it++) {
                int k = lane + it * 32;
                float hv = s_h[k * SPAD + m];
                aq0 += hv * qw[k];
                aq1 += hv * qw[HID + k];
                aq2 += hv * qw[2 * HID + k];
                aq3 += hv * qw[3 * HID + k];
                av0 += hv * vw[k];
                av1 += hv * vw[HID + k];
                av2 += hv * vw[2 * HID + k];
                ac0 += hv * cw[k];
                ac1 += hv * cw[HID + k];
                ac2 += hv * cw[2 * HID + k];
            }
#pragma unroll
            for (int off = 16; off > 0; off >>= 1) {
                aq0 += __shfl_xor_sync(0xffffffffu, aq0, off);
                aq1 += __shfl_xor_sync(0xffffffffu, aq1, off);
                aq2 += __shfl_xor_sync(0xffffffffu, aq2, off);
                aq3 += __shfl_xor_sync(0xffffffffu, aq3, off);
                av0 += __shfl_xor_sync(0xffffffffu, av0, off);
                av1 += __shfl_xor_sync(0xffffffffu, av1, off);
                av2 += __shfl_xor_sync(0xffffffffu, av2, off);
                ac0 += __shfl_xor_sync(0xffffffffu, ac0, off);
                ac1 += __shfl_xor_sync(0xffffffffu, ac1, off);
                ac2 += __shfl_xor_sync(0xffffffffu, ac2, off);
            }
            if (lane == 0) {
                float q0 = aq0 + qb[0], q1 = aq1 + qb[1];
                float q2 = aq2 + qb[2], q3 = aq3 + qb[3];
                float nrm = sqrtf(q0 * q0 + q1 * q1 + q2 * q2 + q3 * q3);
                nrm = fmaxf(nrm, 1e-12f);
                float w = q0 / nrm, xq = q1 / nrm, yq = q2 / nrm, zq = q3 / nrm;
                float xx = xq * xq, yy = yq * yq, zz = zq * zq;
                float xy = xq * yq, xz = xq * zq, yz = yq * zq;
                float wx = w * xq, wy = w * yq, wz2 = w * zq;
                float a0 = s_x[m * IND + 0], a1 = s_x[m * IND + 1], a2 = s_x[m * IND + 2];
                float dt = s_x[m * IND + (IND - 1)];
                float aw0 = (1.f - 2.f * (yy + zz)) * a0 + 2.f * (xy - wz2) * a1 + 2.f * (xz + wy) * a2;
                float aw1 = 2.f * (xy + wz2) * a0 + (1.f - 2.f * (xx + zz)) * a1 + 2.f * (yz - wx) * a2;
                float aw2 = 2.f * (xz - wy) * a0 + 2.f * (yz + wx) * a1 + (1.f - 2.f * (xx + yy)) * a2;
                float v0 = av0 + vb[0], v1 = av1 + vb[1], v2 = av2 + vb[2];
                float e0 = ac0 + cb[0], e1 = ac1 + cb[1], e2 = ac2 + cb[2];
                float hdt2 = 0.5f * dt * dt;
                dp0 += v0 * dt + aw0 * hdt2 + e0;
                dp1 += v1 * dt + aw1 * hdt2 + e1;
                dp2 += v2 * dt + aw2 * hdt2 + e2;
            }
        }
    }

    if (lane == 0) {
        size_t ob = (size_t)(b0 + m) * 3;
        dp_out[ob + 0] = dp0;
        dp_out[ob + 1] = dp1;
        dp_out[ob + 2] = dp2;
    }
}

extern "C" void kernel_launch(void* const* d_in, const int* in_sizes, int n_in,
                              void* d_out, int out_size) {
    (void)in_sizes; (void)n_in; (void)out_size;
    const float* x   = (const float*)d_in[0];
    const float* h0  = (const float*)d_in[1];
    const float* w1  = (const float*)d_in[2];
    const float* b1  = (const float*)d_in[3];
    const float* w2  = (const float*)d_in[4];
    const float* b2  = (const float*)d_in[5];
    const float* wih = (const float*)d_in[6];
    const float* whh = (const float*)d_in[7];
    const float* bih = (const float*)d_in[8];
    const float* bhh = (const float*)d_in[9];
    const float* qw  = (const float*)d_in[10];
    const float* qb  = (const float*)d_in[11];
    const float* vw  = (const float*)d_in[12];
    const float* vb  = (const float*)d_in[13];
    const float* cw  = (const float*)d_in[14];
    const float* cb  = (const float*)d_in[15];
    float* out = (float*)d_out;

    const size_t smem_bytes =
        (size_t)(HID * SPAD + KIH * SPAD + LATD * SPAD + MB * IND) * sizeof(float);

    cudaFuncSetAttribute(imu_persistent_kernel,
                         cudaFuncAttributeMaxDynamicSharedMemorySize,
                         (int)smem_bytes);

    transpose_weights_kernel<<<256, 256>>>(w1, w2, wih, whh);
    imu_persistent_kernel<<<NBLK, NTHR, smem_bytes>>>(
        x, h0, out, b1, b2, bih, bhh, qw, qb, vw, vb, cw, cb);
}

// round 6
// speedup vs baseline: 1.2707x; 1.0000x over previous
#include <cuda_runtime.h>
#include <math.h>
#include <stddef.h>

typedef unsigned long long ull;

#define Bq   4096
#define Tt   512
#define IND  17
#define LATD 256
#define HID  512
#define G3   1536
#define KIH  257          // LATD + 1 (dt)
#define MB   16           // batch rows per block
#define NBLK (Bq / MB)    // 256 blocks
#define NTHR 512
#define SPAD 20           // smem row pad (floats): 80B rows -> 16B-aligned

// ---- device scratch (static, no runtime allocation) ----
// +1 padded row on each transposed weight array: the software-pipelined
// prefetch reads one row past the end on the final iteration (values unused).
__device__ float g_w1T[IND * LATD];            // [k][j]
__device__ float g_w2T[(LATD + 1) * LATD];     // [k][j] (+pad row)
__device__ float g_wihT[(KIH + 1) * G3];       // [k][j] (+pad row)
__device__ float g_whhT[(HID + 1) * G3];       // [k][j] (+pad row)

// ---- packed f32x2 helpers (Blackwell FFMA2 — ptxas never emits these) ----
__device__ __forceinline__ ull pack2(float v) {
    ull r;
    asm("mov.b64 %0, {%1, %1};" : "=l"(r) : "f"(v));
    return r;
}
__device__ __forceinline__ void fma2(ull& d, ull a, ull b) {
    asm("fma.rn.f32x2 %0, %1, %2, %0;" : "+l"(d) : "l"(a), "l"(b));
}
__device__ __forceinline__ float2 unpack2(ull v) {
    float2 f;
    asm("mov.b64 {%0, %1}, %2;" : "=f"(f.x), "=f"(f.y) : "l"(v));
    return f;
}

// ---- one-time weight transpose ----
__global__ void transpose_weights_kernel(const float* __restrict__ w1,
                                         const float* __restrict__ w2,
                                         const float* __restrict__ wih,
                                         const float* __restrict__ whh) {
    int i = blockIdx.x * blockDim.x + threadIdx.x;
    int stride = gridDim.x * blockDim.x;
    for (int o = i; o < IND * LATD; o += stride) {
        int k = o / LATD, j = o % LATD;
        g_w1T[o] = w1[j * IND + k];
    }
    for (int o = i; o < LATD * LATD; o += stride) {
        int k = o / LATD, j = o % LATD;
        g_w2T[o] = w2[j * LATD + k];
    }
    for (int o = i; o < KIH * G3; o += stride) {
        int k = o / G3, j = o % G3;
        g_wihT[o] = wih[j * KIH + k];
    }
    for (int o = i; o < HID * G3; o += stride) {
        int k = o / G3, j = o % G3;
        g_whhT[o] = whh[j * HID + k];
    }
}

__device__ __forceinline__ float sigmoidf_acc(float v) {
    return 1.0f / (1.0f + expf(-v));
}

// ---- persistent fused kernel: each block owns a 16-sample batch tile for all
// 512 timesteps. h lives in SMEM across the whole sequence; dp accumulates in
// registers; one global write at the end. Blocks are fully independent. ----
__global__ void __launch_bounds__(NTHR, 1)
imu_persistent_kernel(const float* __restrict__ x,
                      const float* __restrict__ h0,
                      float* __restrict__ dp_out,
                      const float* __restrict__ b1, const float* __restrict__ b2,
                      const float* __restrict__ bih, const float* __restrict__ bhh,
                      const float* __restrict__ qw, const float* __restrict__ qb,
                      const float* __restrict__ vw, const float* __restrict__ vb,
                      const float* __restrict__ cw, const float* __restrict__ cb) {
    extern __shared__ float sm[];
    float* s_h   = sm;                       // [HID][SPAD]  h, k-major
    float* s_gin = s_h + HID * SPAD;         // [KIH][SPAD]  encoder output + dt
    float* s_z1  = s_gin + KIH * SPAD;       // [LATD][SPAD] encoder layer-1
    float* s_x   = s_z1 + LATD * SPAD;       // [MB][IND]    raw x tile

    const int tid  = threadIdx.x;
    const int b0   = blockIdx.x * MB;
    const int j    = tid & (LATD - 1);
    const int mb   = (tid >> 8) * 8;         // encoder row group: 0 or 8
    const int jj   = tid;                    // hidden unit owned in gate GEMM
    const int lane = tid & 31;
    const int m    = tid >> 5;               // sample owned in heads stage

    // hoisted per-thread constants
    const float bj1 = b1[j];
    const float bj2 = b2[j];
    const float br  = bih[jj]           + bhh[jj];
    const float bz  = bih[jj + HID]     + bhh[jj + HID];
    const float bni = bih[jj + 2 * HID];
    const float bnh = bhh[jj + 2 * HID];

    float dp0 = 0.f, dp1 = 0.f, dp2 = 0.f;   // lane 0 of each warp holds sample m's dp

    // load h0 once (transposed into SMEM)
    for (int idx = tid; idx < MB * HID; idx += NTHR) {
        int mm = idx >> 9;
        int k  = idx & (HID - 1);
        s_h[k * SPAD + mm] = h0[(size_t)(b0 + mm) * HID + k];
    }

    for (int t = 0; t < Tt; t++) {
        __syncthreads();  // protect s_x / s_z1 / s_gin vs previous step's readers

        // ---- stage 0: load x tile ----
        for (int idx = tid; idx < MB * IND; idx += NTHR) {
            int mm = idx / IND, c = idx % IND;
            s_x[idx] = x[((size_t)(b0 + mm) * Tt + t) * IND + c];
        }
        __syncthreads();

        // ---- stage 1: z1 = relu(x @ w1^T + b1) ----
        {
            float acc[8];
#pragma unroll
            for (int i = 0; i < 8; i++) acc[i] = 0.0f;
#pragma unroll
            for (int k = 0; k < IND; k++) {
                float w = g_w1T[k * LATD + j];
#pragma unroll
                for (int i = 0; i < 8; i++) acc[i] += s_x[(mb + i) * IND + k] * w;
            }
#pragma unroll
            for (int i = 0; i < 8; i++)
                s_z1[j * SPAD + mb + i] = fmaxf(acc[i] + bj1, 0.0f);
        }
        __syncthreads();

        // ---- stage 2: lat = relu(z1 @ w2^T + b2) -> s_gin (packed f32x2) ----
        {
            ull acc[4];
#pragma unroll
            for (int i = 0; i < 4; i++) acc[i] = 0ULL;
            const float* wp = g_w2T + j;
            float w = wp[0];
            for (int k = 0; k < LATD; k++) {
                float wnext = wp[LATD];  // prefetch (pad row on last iter)
                ull w2 = pack2(w);
                const ulonglong2* z2 =
                    reinterpret_cast<const ulonglong2*>(s_z1 + k * SPAD + mb);
                ulonglong2 a = z2[0], b = z2[1];
                fma2(acc[0], a.x, w2);
                fma2(acc[1], a.y, w2);
                fma2(acc[2], b.x, w2);
                fma2(acc[3], b.y, w2);
                w = wnext;
                wp += LATD;
            }
#pragma unroll
            for (int i = 0; i < 4; i++) {
                float2 f = unpack2(acc[i]);
                s_gin[j * SPAD + mb + 2 * i]     = fmaxf(f.x + bj2, 0.0f);
                s_gin[j * SPAD + mb + 2 * i + 1] = fmaxf(f.y + bj2, 0.0f);
            }
        }
        if (tid < MB) {
            s_gin[LATD * SPAD + tid] = s_x[tid * IND + (IND - 1)];  // dt row (k=256)
        }
        __syncthreads();

        // ---- stage 3: fused gate GEMMs (packed f32x2), thread jj owns 16 rows ----
        ull ar2[8], az2[8], an2[8], hn2[8];
        {
            ull brp = pack2(br), bzp = pack2(bz), bnp = pack2(bni);
#pragma unroll
            for (int i = 0; i < 8; i++) {
                ar2[i] = brp; az2[i] = bzp; an2[i] = bnp; hn2[i] = 0ULL;
            }
        }
        // input side: k over gin (257) -> ar/az/an
        {
            const float* wp = g_wihT + jj;
            const float* gp = s_gin;
            float wr = wp[0], wz = wp[HID], wn = wp[2 * HID];
            for (int k = 0; k < KIH; k++) {
                const float* wq = wp + G3;
                float nwr = wq[0], nwz = wq[HID], nwn = wq[2 * HID];  // prefetch
                ull wr2 = pack2(wr), wz2 = pack2(wz), wn2 = pack2(wn);
                const ulonglong2* g2 = reinterpret_cast<const ulonglong2*>(gp);
                ulonglong2 p0 = g2[0], p1 = g2[1], p2 = g2[2], p3 = g2[3];
                fma2(ar2[0], p0.x, wr2); fma2(az2[0], p0.x, wz2); fma2(an2[0], p0.x, wn2);
                fma2(ar2[1], p0.y, wr2); fma2(az2[1], p0.y, wz2); fma2(an2[1], p0.y, wn2);
                fma2(ar2[2], p1.x, wr2); fma2(az2[2], p1.x, wz2); fma2(an2[2], p1.x, wn2);
                fma2(ar2[3], p1.y, wr2); fma2(az2[3], p1.y, wz2); fma2(an2[3], p1.y, wn2);
                fma2(ar2[4], p2.x, wr2); fma2(az2[4], p2.x, wz2); fma2(an2[4], p2.x, wn2);
                fma2(ar2[5], p2.y, wr2); fma2(az2[5], p2.y, wz2); fma2(an2[5], p2.y, wn2);
                fma2(ar2[6], p3.x, wr2); fma2(az2[6], p3.x, wz2); fma2(an2[6], p3.x, wn2);
                fma2(ar2[7], p3.y, wr2); fma2(az2[7], p3.y, wz2); fma2(an2[7], p3.y, wn2);
                wr = nwr; wz = nwz; wn = nwn;
                wp = wq;
                gp += SPAD;
            }
        }
        // recurrent side: k over h (512) -> ar/az/hn
        {
            const float* wp = g_whhT + jj;
            const float* hp = s_h;
            float wr = wp[0], wz = wp[HID], wn = wp[2 * HID];
            for (int k = 0; k < HID; k++) {
                const float* wq = wp + G3;
                float nwr = wq[0], nwz = wq[HID], nwn = wq[2 * HID];  // prefetch
                ull wr2 = pack2(wr), wz2 = pack2(wz), wn2 = pack2(wn);
                const ulonglong2* h2 = reinterpret_cast<const ulonglong2*>(hp);
                ulonglong2 p0 = h2[0], p1 = h2[1], p2 = h2[2], p3 = h2[3];
                fma2(ar2[0], p0.x, wr2); fma2(az2[0], p0.x, wz2); fma2(hn2[0], p0.x, wn2);
                fma2(ar2[1], p0.y, wr2); fma2(az2[1], p0.y, wz2); fma2(hn2[1], p0.y, wn2);
                fma2(ar2[2], p1.x, wr2); fma2(az2[2], p1.x, wz2); fma2(hn2[2], p1.x, wn2);
                fma2(ar2[3], p1.y, wr2); fma2(az2[3], p1.y, wz2); fma2(hn2[3], p1.y, wn2);
                fma2(ar2[4], p2.x, wr2); fma2(az2[4], p2.x, wz2); fma2(hn2[4], p2.x, wn2);
                fma2(ar2[5], p2.y, wr2); fma2(az2[5], p2.y, wz2); fma2(hn2[5], p2.y, wn2);
                fma2(ar2[6], p3.x, wr2); fma2(az2[6], p3.x, wz2); fma2(hn2[6], p3.x, wn2);
                fma2(ar2[7], p3.y, wr2); fma2(az2[7], p3.y, wz2); fma2(hn2[7], p3.y, wn2);
                wr = nwr; wz = nwz; wn = nwn;
                wp = wq;
                hp += SPAD;
            }
        }

        // ---- GRU update ----
        float hnew[MB];
#pragma unroll
        for (int i = 0; i < 8; i++) {
            float2 fr = unpack2(ar2[i]);
            float2 fz = unpack2(az2[i]);
            float2 fn = unpack2(an2[i]);
            float2 fh = unpack2(hn2[i]);
            {
                float r    = sigmoidf_acc(fr.x);
                float z    = sigmoidf_acc(fz.x);
                float n    = tanhf(fn.x + r * (fh.x + bnh));
                float hold = s_h[jj * SPAD + 2 * i];
                hnew[2 * i] = (1.0f - z) * n + z * hold;
            }
            {
                float r    = sigmoidf_acc(fr.y);
                float z    = sigmoidf_acc(fz.y);
                float n    = tanhf(fn.y + r * (fh.y + bnh));
                float hold = s_h[jj * SPAD + 2 * i + 1];
                hnew[2 * i + 1] = (1.0f - z) * n + z * hold;
            }
        }
        __syncthreads();  // everyone done reading old s_h
#pragma unroll
        for (int mm = 0; mm < MB; mm++) s_h[jj * SPAD + mm] = hnew[mm];
        __syncthreads();

        // ---- stage 4: heads. one warp per sample; lane0 accumulates dp ----
        {
            float aq0 = 0.f, aq1 = 0.f, aq2 = 0.f, aq3 = 0.f;
            float av0 = 0.f, av1 = 0.f, av2 = 0.f;
            float ac0 = 0.f, ac1 = 0.f, ac2 = 0.f;
#pragma unroll
            for (int it = 0; it < HID / 32; it++) {
                int k = lane + it * 32;
                float hv = s_h[k * SPAD + m];
                aq0 += hv * qw[k];
                aq1 += hv * qw[HID + k];
                aq2 += hv * qw[2 * HID + k];
                aq3 += hv * qw[3 * HID + k];
                av0 += hv * vw[k];
                av1 += hv * vw[HID + k];
                av2 += hv * vw[2 * HID + k];
                ac0 += hv * cw[k];
                ac1 += hv * cw[HID + k];
                ac2 += hv * cw[2 * HID + k];
            }
#pragma unroll
            for (int off = 16; off > 0; off >>= 1) {
                aq0 += __shfl_xor_sync(0xffffffffu, aq0, off);
                aq1 += __shfl_xor_sync(0xffffffffu, aq1, off);
                aq2 += __shfl_xor_sync(0xffffffffu, aq2, off);
                aq3 += __shfl_xor_sync(0xffffffffu, aq3, off);
                av0 += __shfl_xor_sync(0xffffffffu, av0, off);
                av1 += __shfl_xor_sync(0xffffffffu, av1, off);
                av2 += __shfl_xor_sync(0xffffffffu, av2, off);
                ac0 += __shfl_xor_sync(0xffffffffu, ac0, off);
                ac1 += __shfl_xor_sync(0xffffffffu, ac1, off);
                ac2 += __shfl_xor_sync(0xffffffffu, ac2, off);
            }
            if (lane == 0) {
                float q0 = aq0 + qb[0], q1 = aq1 + qb[1];
                float q2 = aq2 + qb[2], q3 = aq3 + qb[3];
                float nrm = sqrtf(q0 * q0 + q1 * q1 + q2 * q2 + q3 * q3);
                nrm = fmaxf(nrm, 1e-12f);
                float w = q0 / nrm, xq = q1 / nrm, yq = q2 / nrm, zq = q3 / nrm;
                float xx = xq * xq, yy = yq * yq, zz = zq * zq;
                float xy = xq * yq, xz = xq * zq, yz = yq * zq;
                float wx = w * xq, wy = w * yq, wz2 = w * zq;
                float a0 = s_x[m * IND + 0], a1 = s_x[m * IND + 1], a2 = s_x[m * IND + 2];
                float dt = s_x[m * IND + (IND - 1)];
                float aw0 = (1.f - 2.f * (yy + zz)) * a0 + 2.f * (xy - wz2) * a1 + 2.f * (xz + wy) * a2;
                float aw1 = 2.f * (xy + wz2) * a0 + (1.f - 2.f * (xx + zz)) * a1 + 2.f * (yz - wx) * a2;
                float aw2 = 2.f * (xz - wy) * a0 + 2.f * (yz + wx) * a1 + (1.f - 2.f * (xx + yy)) * a2;
                float v0 = av0 + vb[0], v1 = av1 + vb[1], v2 = av2 + vb[2];
                float e0 = ac0 + cb[0], e1 = ac1 + cb[1], e2 = ac2 + cb[2];
                float hdt2 = 0.5f * dt * dt;
                dp0 += v0 * dt + aw0 * hdt2 + e0;
                dp1 += v1 * dt + aw1 * hdt2 + e1;
                dp2 += v2 * dt + aw2 * hdt2 + e2;
            }
        }
    }

    if (lane == 0) {
        size_t ob = (size_t)(b0 + m) * 3;
        dp_out[ob + 0] = dp0;
        dp_out[ob + 1] = dp1;
        dp_out[ob + 2] = dp2;
    }
}

extern "C" void kernel_launch(void* const* d_in, const int* in_sizes, int n_in,
                              void* d_out, int out_size) {
    (void)in_sizes; (void)n_in; (void)out_size;
    const float* x   = (const float*)d_in[0];
    const float* h0  = (const float*)d_in[1];
    const float* w1  = (const float*)d_in[2];
    const float* b1  = (const float*)d_in[3];
    const float* w2  = (const float*)d_in[4];
    const float* b2  = (const float*)d_in[5];
    const float* wih = (const float*)d_in[6];
    const float* whh = (const float*)d_in[7];
    const float* bih = (const float*)d_in[8];
    const float* bhh = (const float*)d_in[9];
    const float* qw  = (const float*)d_in[10];
    const float* qb  = (const float*)d_in[11];
    const float* vw  = (const float*)d_in[12];
    const float* vb  = (const float*)d_in[13];
    const float* cw  = (const float*)d_in[14];
    const float* cb  = (const float*)d_in[15];
    float* out = (float*)d_out;

    const size_t smem_bytes =
        (size_t)(HID * SPAD + KIH * SPAD + LATD * SPAD + MB * IND) * sizeof(float);

    cudaFuncSetAttribute(imu_persistent_kernel,
                         cudaFuncAttributeMaxDynamicSharedMemorySize,
                         (int)smem_bytes);

    transpose_weights_kernel<<<256, 256>>>(w1, w2, wih, whh);
    imu_persistent_kernel<<<NBLK, NTHR, smem_bytes>>>(
        x, h0, out, b1, b2, bih, bhh, qw, qb, vw, vb, cw, cb);
}